// round 5
// baseline (speedup 1.0000x reference)
#include <cuda_runtime.h>
#include <cuda_bf16.h>
#include <math.h>

// Problem constants
#define B_DIM 4096
#define T_DIM 2048
#define N_ELEM (B_DIM * T_DIM)           // 8,388,608
static __device__ __constant__ const float kGamma   = 0.99f;
static __device__ __constant__ const float kGL      = (float)(0.99 * 0.95);  // gamma*lam
static __device__ __constant__ const float kEps     = 1e-9f;

// Accumulators + scratch (no allocations allowed -> __device__ globals)
__device__ double g_S1;    // sum(adv_raw)
__device__ double g_S2;    // sum(adv_raw^2)  == N * value_loss
__device__ double g_MIN;   // sum(min(surr1, surr2))
__device__ double g_ENT;   // sum(curr * log(curr + eps))
__device__ float  g_adv[N_ELEM];

__global__ void ppo_init_kernel() {
    g_S1 = 0.0; g_S2 = 0.0; g_MIN = 0.0; g_ENT = 0.0;
}

// ---------------------------------------------------------------------------
// Pass 1: GAE reverse scan (one CTA per row), write adv, accumulate S1/S2.
// Linear recurrence adv_t = delta_t + c_t * adv_{t+1}; composed as (A,P)
// pairs meaning x -> A + P*x, higher-t segments applied first.
// ---------------------------------------------------------------------------
__global__ __launch_bounds__(256, 1)
void ppo_gae_kernel(const float* __restrict__ rewards,
                    const float* __restrict__ values,
                    const float* __restrict__ masks)
{
    const int b   = blockIdx.x;
    const int tid = threadIdx.x;
    const int lane = tid & 31;
    const int warp = tid >> 5;
    const int t0  = tid << 3;                 // 8 elements per thread

    const float* rr = rewards + (size_t)b * T_DIM + t0;
    const float* mm = masks   + (size_t)b * T_DIM + t0;
    const float* vv = values  + (size_t)b * (T_DIM + 1) + t0;

    float4 rA = *(const float4*)(rr);
    float4 rB = *(const float4*)(rr + 4);
    float4 mA = *(const float4*)(mm);
    float4 mB = *(const float4*)(mm + 4);
    float r[8] = {rA.x, rA.y, rA.z, rA.w, rB.x, rB.y, rB.z, rB.w};
    float m[8] = {mA.x, mA.y, mA.z, mA.w, mB.x, mB.y, mB.z, mB.w};

    float v[9];
    #pragma unroll
    for (int j = 0; j < 9; ++j) v[j] = __ldg(vv + j);   // row stride 2049: scalar loads

    float delta[8], c[8];
    #pragma unroll
    for (int j = 0; j < 8; ++j) {
        delta[j] = r[j] + kGamma * v[j + 1] * m[j] - v[j];
        c[j]     = kGL * m[j];
    }

    // Thread-local reverse scan with zero carry -> summary (A, P)
    float A = 0.f, P = 1.f;
    #pragma unroll
    for (int j = 7; j >= 0; --j) { A = delta[j] + c[j] * A; P *= c[j]; }

    // Warp inclusive SUFFIX scan (higher lanes = higher t = applied first)
    const unsigned full = 0xffffffffu;
    float Ai = A, Pi = P;
    #pragma unroll
    for (int d = 1; d < 32; d <<= 1) {
        float Ah = __shfl_down_sync(full, Ai, d);
        float Ph = __shfl_down_sync(full, Pi, d);
        if (lane + d < 32) { Ai = Ai + Pi * Ah; Pi = Pi * Ph; }
    }

    __shared__ float wA[8], wP[8];
    if (lane == 0) { wA[warp] = Ai; wP[warp] = Pi; }
    __syncthreads();

    // Carry value entering this warp: compose warps 7..warp+1 applied to 0
    float warpCarry = 0.f;
    for (int w = 7; w > warp; --w) warpCarry = wA[w] + wP[w] * warpCarry;

    // Exclusive-within-warp transform = inclusive suffix of lane+1
    float Ae = __shfl_down_sync(full, Ai, 1);
    float Pe = __shfl_down_sync(full, Pi, 1);
    if (lane == 31) { Ae = 0.f; Pe = 1.f; }
    float carry = Ae + Pe * warpCarry;

    // Final local values with real carry
    float av[8];
    float a = carry;
    #pragma unroll
    for (int j = 7; j >= 0; --j) { a = delta[j] + c[j] * a; av[j] = a; }

    // Store adv (coalesced float4)
    float* ao = g_adv + (size_t)b * T_DIM + t0;
    *(float4*)(ao)     = make_float4(av[0], av[1], av[2], av[3]);
    *(float4*)(ao + 4) = make_float4(av[4], av[5], av[6], av[7]);

    // Block reduce sum / sumsq (double across threads)
    float fs = 0.f, fq = 0.f;
    #pragma unroll
    for (int j = 0; j < 8; ++j) { fs += av[j]; fq += av[j] * av[j]; }
    double ls = (double)fs, lq = (double)fq;
    #pragma unroll
    for (int d = 16; d > 0; d >>= 1) {
        ls += __shfl_down_sync(full, ls, d);
        lq += __shfl_down_sync(full, lq, d);
    }
    __shared__ double sA[8], sB[8];
    if (lane == 0) { sA[warp] = ls; sB[warp] = lq; }
    __syncthreads();
    if (tid == 0) {
        double ts = 0.0, tq = 0.0;
        #pragma unroll
        for (int w = 0; w < 8; ++w) { ts += sA[w]; tq += sB[w]; }
        atomicAdd(&g_S1, ts);
        atomicAdd(&g_S2, tq);
    }
}

// ---------------------------------------------------------------------------
// Pass 2: normalize adv, PPO clipped-surrogate min + entropy, reduce.
// min(surr1,surr2) = a>=0 ? min(ratio,1.2)*a : max(ratio,0.8)*a
// ---------------------------------------------------------------------------
__global__ __launch_bounds__(256, 1)
void ppo_loss_kernel(const float* __restrict__ oldp,
                     const float* __restrict__ currp)
{
    __shared__ float s_mean, s_scale;
    if (threadIdx.x == 0) {
        const double N = (double)N_ELEM;
        double mean = g_S1 / N;
        double var  = (g_S2 - N * mean * mean) / (N - 1.0);   // ddof=1
        s_mean  = (float)mean;
        s_scale = (float)(1.0 / (sqrt(var) + 1e-9));
    }
    __syncthreads();
    const float mean  = s_mean;
    const float scale = s_scale;

    const int n4 = N_ELEM / 4;
    double lmin = 0.0, lent = 0.0;

    for (int i = blockIdx.x * blockDim.x + threadIdx.x; i < n4;
         i += gridDim.x * blockDim.x) {
        float4 a4 = ((const float4*)g_adv)[i];
        float4 o4 = __ldg((const float4*)oldp + i);
        float4 c4 = __ldg((const float4*)currp + i);
        float av[4] = {a4.x, a4.y, a4.z, a4.w};
        float ov[4] = {o4.x, o4.y, o4.z, o4.w};
        float cv[4] = {c4.x, c4.y, c4.z, c4.w};

        float fm = 0.f, fe = 0.f;
        #pragma unroll
        for (int k = 0; k < 4; ++k) {
            float an = (av[k] - mean) * scale;
            float ratio = __fdividef(cv[k], ov[k] + kEps);
            float t = (an >= 0.f) ? fminf(ratio, 1.2f) * an
                                  : fmaxf(ratio, 0.8f) * an;
            fm += t;
            fe += cv[k] * __logf(cv[k] + kEps);
        }
        lmin += (double)fm;
        lent += (double)fe;
    }

    const unsigned full = 0xffffffffu;
    #pragma unroll
    for (int d = 16; d > 0; d >>= 1) {
        lmin += __shfl_down_sync(full, lmin, d);
        lent += __shfl_down_sync(full, lent, d);
    }
    __shared__ double sM[8], sE[8];
    const int lane = threadIdx.x & 31, warp = threadIdx.x >> 5;
    if (lane == 0) { sM[warp] = lmin; sE[warp] = lent; }
    __syncthreads();
    if (threadIdx.x == 0) {
        double tm = 0.0, te = 0.0;
        #pragma unroll
        for (int w = 0; w < 8; ++w) { tm += sM[w]; te += sE[w]; }
        atomicAdd(&g_MIN, tm);
        atomicAdd(&g_ENT, te);
    }
}

__global__ void ppo_finalize_kernel(float* __restrict__ out)
{
    const double N = (double)N_ELEM;
    double ppo = -(g_MIN / N);
    double vl  = 0.5 * (g_S2 / N);          // VALUE_LOSS_COEF * mean(adv_raw^2)
    double ent = -0.01 * (g_ENT / N);       // ENTROPY_COEF * entropy_loss
    out[0] = (float)(ppo + vl + ent);
    out[1] = (float)ppo;
    out[2] = (float)vl;
    out[3] = (float)ent;
}

extern "C" void kernel_launch(void* const* d_in, const int* in_sizes, int n_in,
                              void* d_out, int out_size)
{
    const float* rewards = (const float*)d_in[0];
    const float* values  = (const float*)d_in[1];
    // d_in[2] = ref_probs (unused by reference)
    const float* oldp    = (const float*)d_in[3];
    const float* currp   = (const float*)d_in[4];
    const float* masks   = (const float*)d_in[5];

    ppo_init_kernel<<<1, 1>>>();
    ppo_gae_kernel<<<B_DIM, 256>>>(rewards, values, masks);
    ppo_loss_kernel<<<1184, 256>>>(oldp, currp);
    ppo_finalize_kernel<<<1, 1>>>((float*)d_out);
}

// round 7
// speedup vs baseline: 1.0861x; 1.0861x over previous
#include <cuda_runtime.h>
#include <cuda_bf16.h>
#include <math.h>

// Problem constants
#define B_DIM 4096
#define T_DIM 2048
#define N_ELEM (B_DIM * T_DIM)           // 8,388,608
#define LOSS_GRID 1184
static __device__ __constant__ const float kGamma = 0.99f;
static __device__ __constant__ const float kGL    = (float)(0.99 * 0.95);  // gamma*lam
static __device__ __constant__ const float kEps   = 1e-9f;

// Accumulators + scratch (no allocations allowed -> __device__ globals).
// Invariant: all accumulators are ZERO on entry to kernel_launch; the
// last CTA of ppo_loss_kernel resets them after producing the output.
__device__ double   g_S1  = 0.0;   // sum(adv_raw)
__device__ double   g_S2  = 0.0;   // sum(adv_raw^2)  == N * value_loss
__device__ double   g_MIN = 0.0;   // sum(min(surr1, surr2))
__device__ double   g_ENT = 0.0;   // sum(curr * log(curr + eps))
__device__ unsigned g_done = 0u;   // CTA arrival counter for pass 2
__device__ float    g_adv[N_ELEM];

// ---------------------------------------------------------------------------
// Pass 1: GAE reverse scan (one CTA per row), write adv, accumulate S1/S2.
// Linear recurrence adv_t = delta_t + c_t * adv_{t+1}; composed as (A,P)
// pairs meaning x -> A + P*x, higher-t segments applied first.
// Streaming inputs use evict-first (__ldcs) so the adv scratch stays in L2.
// ---------------------------------------------------------------------------
__global__ __launch_bounds__(256, 1)
void ppo_gae_kernel(const float* __restrict__ rewards,
                    const float* __restrict__ values,
                    const float* __restrict__ masks)
{
    const int b    = blockIdx.x;
    const int tid  = threadIdx.x;
    const int lane = tid & 31;
    const int warp = tid >> 5;
    const int t0   = tid << 3;                 // 8 elements per thread

    const float* rr = rewards + (size_t)b * T_DIM + t0;
    const float* mm = masks   + (size_t)b * T_DIM + t0;
    const float* vv = values  + (size_t)b * (T_DIM + 1) + t0;

    float4 rA = __ldcs((const float4*)(rr));
    float4 rB = __ldcs((const float4*)(rr + 4));
    float4 mA = __ldcs((const float4*)(mm));
    float4 mB = __ldcs((const float4*)(mm + 4));
    float r[8] = {rA.x, rA.y, rA.z, rA.w, rB.x, rB.y, rB.z, rB.w};
    float m[8] = {mA.x, mA.y, mA.z, mA.w, mB.x, mB.y, mB.z, mB.w};

    float v[9];
    #pragma unroll
    for (int j = 0; j < 9; ++j) v[j] = __ldcs(vv + j);  // row stride 2049

    float delta[8], c[8];
    #pragma unroll
    for (int j = 0; j < 8; ++j) {
        delta[j] = r[j] + kGamma * v[j + 1] * m[j] - v[j];
        c[j]     = kGL * m[j];
    }

    // Thread-local reverse scan with zero carry -> summary (A, P)
    float A = 0.f, P = 1.f;
    #pragma unroll
    for (int j = 7; j >= 0; --j) { A = delta[j] + c[j] * A; P *= c[j]; }

    // Warp inclusive SUFFIX scan (higher lanes = higher t = applied first)
    const unsigned full = 0xffffffffu;
    float Ai = A, Pi = P;
    #pragma unroll
    for (int d = 1; d < 32; d <<= 1) {
        float Ah = __shfl_down_sync(full, Ai, d);
        float Ph = __shfl_down_sync(full, Pi, d);
        if (lane + d < 32) { Ai = Ai + Pi * Ah; Pi = Pi * Ph; }
    }

    __shared__ float wA[8], wP[8];
    if (lane == 0) { wA[warp] = Ai; wP[warp] = Pi; }
    __syncthreads();

    // Carry value entering this warp: compose warps 7..warp+1 applied to 0
    float warpCarry = 0.f;
    for (int w = 7; w > warp; --w) warpCarry = wA[w] + wP[w] * warpCarry;

    // Exclusive-within-warp transform = inclusive suffix of lane+1
    float Ae = __shfl_down_sync(full, Ai, 1);
    float Pe = __shfl_down_sync(full, Pi, 1);
    if (lane == 31) { Ae = 0.f; Pe = 1.f; }
    float carry = Ae + Pe * warpCarry;

    // Final local values with real carry
    float av[8];
    float a = carry;
    #pragma unroll
    for (int j = 7; j >= 0; --j) { a = delta[j] + c[j] * a; av[j] = a; }

    // Store adv (coalesced float4, default policy -> L2 resident for pass 2)
    float* ao = g_adv + (size_t)b * T_DIM + t0;
    *(float4*)(ao)     = make_float4(av[0], av[1], av[2], av[3]);
    *(float4*)(ao + 4) = make_float4(av[4], av[5], av[6], av[7]);

    // Block reduce sum / sumsq (double across threads)
    float fs = 0.f, fq = 0.f;
    #pragma unroll
    for (int j = 0; j < 8; ++j) { fs += av[j]; fq += av[j] * av[j]; }
    double ls = (double)fs, lq = (double)fq;
    #pragma unroll
    for (int d = 16; d > 0; d >>= 1) {
        ls += __shfl_down_sync(full, ls, d);
        lq += __shfl_down_sync(full, lq, d);
    }
    __shared__ double sA[8], sB[8];
    if (lane == 0) { sA[warp] = ls; sB[warp] = lq; }
    __syncthreads();
    if (tid == 0) {
        double ts = 0.0, tq = 0.0;
        #pragma unroll
        for (int w = 0; w < 8; ++w) { ts += sA[w]; tq += sB[w]; }
        atomicAdd(&g_S1, ts);
        atomicAdd(&g_S2, tq);
    }
}

// ---------------------------------------------------------------------------
// Pass 2: normalize adv, PPO clipped-surrogate min + entropy, reduce,
// and (last CTA) finalize output + reset accumulators for the next call.
// min(surr1,surr2) = a>=0 ? min(ratio,1.2)*a : max(ratio,0.8)*a
// ---------------------------------------------------------------------------
__global__ __launch_bounds__(256, 1)
void ppo_loss_kernel(const float* __restrict__ oldp,
                     const float* __restrict__ currp,
                     float* __restrict__ out)
{
    __shared__ float s_mean, s_scale;
    if (threadIdx.x == 0) {
        const double N = (double)N_ELEM;
        double mean = g_S1 / N;
        double var  = (g_S2 - N * mean * mean) / (N - 1.0);   // ddof=1
        s_mean  = (float)mean;
        s_scale = (float)(1.0 / (sqrt(var) + 1e-9));
    }
    __syncthreads();
    const float mean  = s_mean;
    const float scale = s_scale;

    const int n4 = N_ELEM / 4;
    double lmin = 0.0, lent = 0.0;

    for (int i = blockIdx.x * blockDim.x + threadIdx.x; i < n4;
         i += gridDim.x * blockDim.x) {
        float4 a4 = __ldlu((const float4*)g_adv + i);   // last-use: no writeback
        float4 o4 = __ldcs((const float4*)oldp + i);    // streaming, evict-first
        float4 c4 = __ldcs((const float4*)currp + i);
        float av[4] = {a4.x, a4.y, a4.z, a4.w};
        float ov[4] = {o4.x, o4.y, o4.z, o4.w};
        float cv[4] = {c4.x, c4.y, c4.z, c4.w};

        float fm = 0.f, fe = 0.f;
        #pragma unroll
        for (int k = 0; k < 4; ++k) {
            float an = (av[k] - mean) * scale;
            float ratio = __fdividef(cv[k], ov[k] + kEps);
            float t = (an >= 0.f) ? fminf(ratio, 1.2f) * an
                                  : fmaxf(ratio, 0.8f) * an;
            fm += t;
            fe += cv[k] * __logf(cv[k] + kEps);
        }
        lmin += (double)fm;
        lent += (double)fe;
    }

    const unsigned full = 0xffffffffu;
    #pragma unroll
    for (int d = 16; d > 0; d >>= 1) {
        lmin += __shfl_down_sync(full, lmin, d);
        lent += __shfl_down_sync(full, lent, d);
    }
    __shared__ double sM[8], sE[8];
    const int lane = threadIdx.x & 31, warp = threadIdx.x >> 5;
    if (lane == 0) { sM[warp] = lmin; sE[warp] = lent; }
    __syncthreads();

    __shared__ int s_last;
    if (threadIdx.x == 0) {
        double tm = 0.0, te = 0.0;
        #pragma unroll
        for (int w = 0; w < 8; ++w) { tm += sM[w]; te += sE[w]; }
        atomicAdd(&g_MIN, tm);
        atomicAdd(&g_ENT, te);
        __threadfence();                 // order loss atomics before arrival
        unsigned arrived = atomicAdd(&g_done, 1u);
        s_last = (arrived == (unsigned)(gridDim.x - 1)) ? 1 : 0;
    }
    __syncthreads();

    // Last CTA: finalize output and reset all accumulators for the next call.
    if (s_last && threadIdx.x == 0) {
        // coherent reads of totals (bypass L1)
        double tmin = atomicAdd(&g_MIN, 0.0);
        double tent = atomicAdd(&g_ENT, 0.0);
        double ts2  = atomicAdd(&g_S2,  0.0);
        const double N = (double)N_ELEM;
        double ppo = -(tmin / N);
        double vl  = 0.5  * (ts2  / N);   // VALUE_LOSS_COEF * mean(adv_raw^2)
        double ent = -0.01 * (tent / N);  // ENTROPY_COEF * entropy_loss
        out[0] = (float)(ppo + vl + ent);
        out[1] = (float)ppo;
        out[2] = (float)vl;
        out[3] = (float)ent;
        // reset state (plain stores; next launch sees them post-boundary)
        g_S1 = 0.0; g_S2 = 0.0; g_MIN = 0.0; g_ENT = 0.0;
        __threadfence();
        g_done = 0u;
    }
}

extern "C" void kernel_launch(void* const* d_in, const int* in_sizes, int n_in,
                              void* d_out, int out_size)
{
    const float* rewards = (const float*)d_in[0];
    const float* values  = (const float*)d_in[1];
    // d_in[2] = ref_probs (unused by reference)
    const float* oldp    = (const float*)d_in[3];
    const float* currp   = (const float*)d_in[4];
    const float* masks   = (const float*)d_in[5];

    ppo_gae_kernel<<<B_DIM, 256>>>(rewards, values, masks);
    ppo_loss_kernel<<<LOSS_GRID, 256>>>(oldp, currp, (float*)d_out);
}

// round 12
// speedup vs baseline: 1.7982x; 1.6557x over previous
#include <cuda_runtime.h>
#include <cuda_bf16.h>
#include <cuda_fp16.h>
#include <math.h>

// Problem constants
#define B_DIM 4096
#define T_DIM 2048
#define N_ELEM (B_DIM * T_DIM)        // 8,388,608
#define GRID   592                     // 148 SMs x 4 CTAs -> guaranteed single wave
#define MAX_ROWS 7                     // ceil(4096/592)
static __device__ __constant__ const float kGamma = 0.99f;
static __device__ __constant__ const float kGL    = (float)(0.99 * 0.95);  // gamma*lam
static __device__ __constant__ const float kEps   = 1e-9f;

// Global state (no allocations allowed -> __device__ globals).
// Invariant: everything is ZERO on entry to each launch; the last CTA to
// finish phase B resets all of it after writing the output.
__device__ double            g_S1  = 0.0;   // sum(adv_raw)
__device__ double            g_S2  = 0.0;   // sum(adv_raw^2) == N * value_loss
__device__ double            g_MIN = 0.0;   // sum(min(surr1, surr2))
__device__ double            g_ENT = 0.0;   // sum(curr * log(curr + eps))
__device__ unsigned          g_arrive1 = 0u;  // phase-A barrier arrivals
__device__ unsigned          g_arrive2 = 0u;  // phase-B completion arrivals
__device__ volatile unsigned g_release = 0u;  // phase-A barrier release flag
__device__ volatile float    g_mean_f  = 0.f;
__device__ volatile float    g_scale_f = 0.f;

// ---------------------------------------------------------------------------
// ONE persistent kernel. Phase A: GAE reverse scan per owned row, advantages
// stashed in SHARED memory (fp16) — never touch DRAM. Grid barrier computes
// mean/std. Phase B: clipped surrogate + entropy from smem adv + prob loads.
// ---------------------------------------------------------------------------
__global__ __launch_bounds__(256, 4)
void ppo_fused_kernel(const float* __restrict__ rewards,
                      const float* __restrict__ values,
                      const float* __restrict__ masks,
                      const float* __restrict__ oldp,
                      const float* __restrict__ currp,
                      float* __restrict__ out)
{
    __shared__ __align__(16) __half s_adv[MAX_ROWS * T_DIM];  // 28 KB
    __shared__ float  wA[8], wP[8];
    __shared__ double sA[8], sB[8];
    __shared__ float  s_mean, s_scale;

    const int bid  = blockIdx.x;
    const int tid  = threadIdx.x;
    const int lane = tid & 31;
    const int warp = tid >> 5;
    const int t0   = tid << 3;                    // 8 elements per thread
    const unsigned full = 0xffffffffu;

    const int nrows = (bid < 544) ? 7 : 6;        // 544*7 + 48*6 = 4096

    // ===================== Phase A: GAE scan per row =====================
    double dS1 = 0.0, dS2 = 0.0;                  // per-thread across rows

    for (int i = 0; i < nrows; ++i) {
        const int b = bid + i * GRID;

        const float* rr = rewards + (size_t)b * T_DIM + t0;
        const float* mm = masks   + (size_t)b * T_DIM + t0;
        const float* vv = values  + (size_t)b * (T_DIM + 1) + t0;

        float4 rA = __ldcs((const float4*)(rr));
        float4 rB = __ldcs((const float4*)(rr + 4));
        float4 mA = __ldcs((const float4*)(mm));
        float4 mB = __ldcs((const float4*)(mm + 4));
        float r[8] = {rA.x, rA.y, rA.z, rA.w, rB.x, rB.y, rB.z, rB.w};
        float m[8] = {mA.x, mA.y, mA.z, mA.w, mB.x, mB.y, mB.z, mB.w};

        float v[9];
        #pragma unroll
        for (int j = 0; j < 9; ++j) v[j] = __ldcs(vv + j);   // row stride 2049

        float delta[8], c[8];
        #pragma unroll
        for (int j = 0; j < 8; ++j) {
            delta[j] = r[j] + kGamma * v[j + 1] * m[j] - v[j];
            c[j]     = kGL * m[j];
        }

        // Thread-local reverse scan summary (A, P): x -> A + P*x
        float A = 0.f, P = 1.f;
        #pragma unroll
        for (int j = 7; j >= 0; --j) { A = delta[j] + c[j] * A; P *= c[j]; }

        // Warp inclusive SUFFIX scan (higher lanes = higher t, applied first)
        float Ai = A, Pi = P;
        #pragma unroll
        for (int d = 1; d < 32; d <<= 1) {
            float Ah = __shfl_down_sync(full, Ai, d);
            float Ph = __shfl_down_sync(full, Pi, d);
            if (lane + d < 32) { Ai = Ai + Pi * Ah; Pi = Pi * Ph; }
        }

        if (lane == 0) { wA[warp] = Ai; wP[warp] = Pi; }
        __syncthreads();

        // Carry entering this warp: compose warps 7..warp+1 applied to 0
        float warpCarry = 0.f;
        #pragma unroll
        for (int w = 7; w >= 0; --w)
            if (w > warp) warpCarry = wA[w] + wP[w] * warpCarry;

        // Exclusive-within-warp transform = inclusive suffix of lane+1
        float Ae = __shfl_down_sync(full, Ai, 1);
        float Pe = __shfl_down_sync(full, Pi, 1);
        if (lane == 31) { Ae = 0.f; Pe = 1.f; }
        float carry = Ae + Pe * warpCarry;

        // Final local values with real carry
        float av[8];
        float a = carry;
        #pragma unroll
        for (int j = 7; j >= 0; --j) { a = delta[j] + c[j] * a; av[j] = a; }

        // Stash advantages in SHARED memory as fp16 (one 16B STS)
        {
            __half2 h01 = __floats2half2_rn(av[0], av[1]);
            __half2 h23 = __floats2half2_rn(av[2], av[3]);
            __half2 h45 = __floats2half2_rn(av[4], av[5]);
            __half2 h67 = __floats2half2_rn(av[6], av[7]);
            uint4 pk;
            pk.x = *reinterpret_cast<unsigned*>(&h01);
            pk.y = *reinterpret_cast<unsigned*>(&h23);
            pk.z = *reinterpret_cast<unsigned*>(&h45);
            pk.w = *reinterpret_cast<unsigned*>(&h67);
            ((uint4*)s_adv)[(i * T_DIM + t0) >> 3] = pk;
        }

        // Accumulate sum/sumsq from full-precision adv (exact value_loss path)
        float fs = 0.f, fq = 0.f;
        #pragma unroll
        for (int j = 0; j < 8; ++j) { fs += av[j]; fq += av[j] * av[j]; }
        dS1 += (double)fs;
        dS2 += (double)fq;

        __syncthreads();   // protect wA/wP before next row overwrites them
    }

    // Block-reduce S1/S2 (double), one atomic pair per CTA
    #pragma unroll
    for (int d = 16; d > 0; d >>= 1) {
        dS1 += __shfl_down_sync(full, dS1, d);
        dS2 += __shfl_down_sync(full, dS2, d);
    }
    if (lane == 0) { sA[warp] = dS1; sB[warp] = dS2; }
    __syncthreads();
    if (tid == 0) {
        double ts = 0.0, tq = 0.0;
        #pragma unroll
        for (int w = 0; w < 8; ++w) { ts += sA[w]; tq += sB[w]; }
        atomicAdd(&g_S1, ts);
        atomicAdd(&g_S2, tq);
    }

    // ===================== Grid-wide barrier + mean/std ==================
    if (tid == 0) {
        __threadfence();                          // order S1/S2 before arrival
        unsigned ticket = atomicAdd(&g_arrive1, 1u);
        if (ticket == (unsigned)(GRID - 1)) {
            // All CTAs arrived; their fences ordered their atomics.
            double ts1 = atomicAdd(&g_S1, 0.0);   // coherent reads
            double ts2 = atomicAdd(&g_S2, 0.0);
            const double N = (double)N_ELEM;
            double mean = ts1 / N;
            double var  = (ts2 - N * mean * mean) / (N - 1.0);  // ddof=1
            g_mean_f  = (float)mean;
            g_scale_f = (float)(1.0 / (sqrt(var) + 1e-9));
            __threadfence();
            g_release = 1u;
        } else {
            while (g_release == 0u) __nanosleep(64);
            __threadfence();
        }
        s_mean  = g_mean_f;
        s_scale = g_scale_f;
    }
    __syncthreads();
    const float mean  = s_mean;
    const float scale = s_scale;

    // ===================== Phase B: surrogate + entropy ==================
    // min(surr1,surr2) = a>=0 ? min(ratio,1.2)*a : max(ratio,0.8)*a
    float fmin_acc = 0.f, fent_acc = 0.f;

    for (int i = 0; i < nrows; ++i) {
        const int b = bid + i * GRID;
        const float4* op = (const float4*)(oldp  + (size_t)b * T_DIM + t0);
        const float4* cp = (const float4*)(currp + (size_t)b * T_DIM + t0);

        uint4  u  = ((const uint4*)s_adv)[(i * T_DIM + t0) >> 3];
        float4 o0 = __ldcs(op);
        float4 o1 = __ldcs(op + 1);
        float4 c0 = __ldcs(cp);
        float4 c1 = __ldcs(cp + 1);

        float2 a01 = __half22float2(*reinterpret_cast<__half2*>(&u.x));
        float2 a23 = __half22float2(*reinterpret_cast<__half2*>(&u.y));
        float2 a45 = __half22float2(*reinterpret_cast<__half2*>(&u.z));
        float2 a67 = __half22float2(*reinterpret_cast<__half2*>(&u.w));

        float av[8] = {a01.x, a01.y, a23.x, a23.y, a45.x, a45.y, a67.x, a67.y};
        float ov[8] = {o0.x, o0.y, o0.z, o0.w, o1.x, o1.y, o1.z, o1.w};
        float cv[8] = {c0.x, c0.y, c0.z, c0.w, c1.x, c1.y, c1.z, c1.w};

        #pragma unroll
        for (int k = 0; k < 8; ++k) {
            float an    = (av[k] - mean) * scale;
            float ratio = __fdividef(cv[k], ov[k] + kEps);
            float t = (an >= 0.f) ? fminf(ratio, 1.2f) * an
                                  : fmaxf(ratio, 0.8f) * an;
            fmin_acc += t;
            fent_acc += cv[k] * __logf(cv[k] + kEps);
        }
    }

    double lmin = (double)fmin_acc, lent = (double)fent_acc;
    #pragma unroll
    for (int d = 16; d > 0; d >>= 1) {
        lmin += __shfl_down_sync(full, lmin, d);
        lent += __shfl_down_sync(full, lent, d);
    }
    if (lane == 0) { sA[warp] = lmin; sB[warp] = lent; }
    __syncthreads();

    if (tid == 0) {
        double tm = 0.0, te = 0.0;
        #pragma unroll
        for (int w = 0; w < 8; ++w) { tm += sA[w]; te += sB[w]; }
        atomicAdd(&g_MIN, tm);
        atomicAdd(&g_ENT, te);
        __threadfence();                  // order loss atomics before arrival
        unsigned done = atomicAdd(&g_arrive2, 1u);
        if (done == (unsigned)(GRID - 1)) {
            // Last CTA: finalize output, reset ALL state for the next launch.
            double tmin = atomicAdd(&g_MIN, 0.0);
            double tent = atomicAdd(&g_ENT, 0.0);
            double ts2  = atomicAdd(&g_S2,  0.0);
            const double N = (double)N_ELEM;
            double ppo = -(tmin / N);
            double vl  = 0.5   * (ts2  / N);  // VALUE_LOSS_COEF * mean(adv^2)
            double ent = -0.01 * (tent / N);  // ENTROPY_COEF * entropy_loss
            out[0] = (float)(ppo + vl + ent);
            out[1] = (float)ppo;
            out[2] = (float)vl;
            out[3] = (float)ent;
            g_S1 = 0.0; g_S2 = 0.0; g_MIN = 0.0; g_ENT = 0.0;
            g_arrive1 = 0u; g_arrive2 = 0u;
            g_mean_f = 0.f; g_scale_f = 0.f;
            __threadfence();
            g_release = 0u;               // safe: every CTA is past barrier 1
        }
    }
}

extern "C" void kernel_launch(void* const* d_in, const int* in_sizes, int n_in,
                              void* d_out, int out_size)
{
    const float* rewards = (const float*)d_in[0];
    const float* values  = (const float*)d_in[1];
    // d_in[2] = ref_probs (unused by reference)
    const float* oldp    = (const float*)d_in[3];
    const float* currp   = (const float*)d_in[4];
    const float* masks   = (const float*)d_in[5];

    ppo_fused_kernel<<<GRID, 256>>>(rewards, values, masks, oldp, currp,
                                    (float*)d_out);
}